// round 6
// baseline (speedup 1.0000x reference)
#include <cuda_runtime.h>
#include <cstdint>
#include <cstddef>

// ============================================================================
// WeaveLayer on sm_100 (no 'a' features): mma.sync m16n8k8 tf32 engine.
//   h = E@We_E + (X@We_Xi)[i] + (X@We_Xj)[j] + be
//   E_new = relu(h)*A ; E_agg[i] = sum_j E_new[i,j]
//   X_new = relu(X@Wn_X + E_agg@Wn_E + bn)
// Output: X_new (65536 f32) then E_new (67108864 f32).
// R6 == R5 resubmit (container infra failure, no data): 256-thr CTAs
// (24 warps/SM), wide k_prep/k_final.
// ============================================================================

#define NN 1024
#define FF 64

__device__ float g_XiB[NN * FF];       // X@We_Xi + be
__device__ float g_XjV[NN * FF];       // X@We_Xj
__device__ float g_Bfrag[64 * 64];     // mma-fragment-ordered tf32 We_E
__device__ float g_part[NN * 8 * FF];  // per (i, j-tile) partial E_agg

// ---------------------------------------------------------------------------
static __device__ __forceinline__ uint32_t smem_u32(const void* p) {
    uint32_t a;
    asm("{ .reg .u64 t; cvta.to.shared.u64 t, %1; cvt.u32.u64 %0, t; }"
        : "=r"(a) : "l"(p));
    return a;
}
static __device__ __forceinline__ uint32_t f2tf32(float x) {
    uint32_t r;
    asm("cvt.rna.tf32.f32 %0, %1;" : "=r"(r) : "f"(x));
    return r;
}
static __device__ __forceinline__ void mma16n8k8(float* c, const uint32_t* a,
                                                 const uint32_t* b) {
    asm volatile(
        "mma.sync.aligned.m16n8k8.row.col.f32.tf32.tf32.f32 "
        "{%0,%1,%2,%3}, {%4,%5,%6,%7}, {%8,%9}, {%0,%1,%2,%3};"
        : "+f"(c[0]), "+f"(c[1]), "+f"(c[2]), "+f"(c[3])
        : "r"(a[0]), "r"(a[1]), "r"(a[2]), "r"(a[3]), "r"(b[0]), "r"(b[1]));
}
static __device__ __forceinline__ void cp_async16(uint32_t dst, const void* src) {
    asm volatile("cp.async.cg.shared.global [%0], [%1], 16;"
                 :: "r"(dst), "l"(src) : "memory");
}
#define CP_COMMIT() asm volatile("cp.async.commit_group;" ::: "memory")
#define CP_WAIT(n)  asm volatile("cp.async.wait_group %0;" :: "n"(n) : "memory")

// ---------------------------------------------------------------------------
// Kernel 1: XiB/XjV + B fragment image. grid = 257 x 256.
// CTA b<256: rows [4b, 4b+4). CTA 256: B fragment image.
// ---------------------------------------------------------------------------
__global__ void __launch_bounds__(256)
k_prep(const float* __restrict__ X, const float* __restrict__ We,
       const float* __restrict__ be) {
    const int b = blockIdx.x, t = threadIdx.x;

    if (b == 256) {
        // g_Bfrag[(k0*8+ni)*64 + lane*2 + h] = tf32(We_E[k0*8+bk+4h][ni*8+bn])
        const int lane = t & 31, grp = t >> 5;
        const int bk = lane & 3, bn = lane >> 2;
        for (int f = grp; f < 64; f += 8) {
            const int k0 = f >> 3, ni = f & 7;
            g_Bfrag[f * 64 + lane * 2 + 0] =
                __uint_as_float(f2tf32(We[(k0 * 8 + bk) * 64 + ni * 8 + bn]));
            g_Bfrag[f * 64 + lane * 2 + 1] =
                __uint_as_float(f2tf32(We[(k0 * 8 + bk + 4) * 64 + ni * 8 + bn]));
        }
        return;
    }

    __shared__ float Ws[8192];   // We_Xi (0..4095), We_Xj (4096..8191)
    __shared__ float Xs[256];
    __shared__ float bes[64];
    const int r0 = b * 4;

    {
        const float4* src = (const float4*)(We + 4096);
        float4* dst = (float4*)Ws;
#pragma unroll
        for (int it = 0; it < 8; ++it) dst[it * 256 + t] = src[it * 256 + t];
    }
    if (t < 64) {
        ((float4*)Xs)[t] = *(const float4*)(X + r0 * 64 + t * 4);
        bes[t] = be[t];
    }
    __syncthreads();

    const int r = t >> 6, col = t & 63;
    float ai = bes[col], aj = 0.f;
#pragma unroll 16
    for (int k = 0; k < 64; ++k) {
        const float v = Xs[r * 64 + k];
        ai += v * Ws[k * 64 + col];
        aj += v * Ws[4096 + k * 64 + col];
    }
    g_XiB[(r0 + r) * 64 + col] = ai;
    g_XjV[(r0 + r) * 64 + col] = aj;
}

// ---------------------------------------------------------------------------
// Kernel 2: edge kernel. One CTA per (i, 128-wide j-tile) = 8192 CTAs,
// 256 threads (8 warps, warp w owns rows [16w,16w+16)).
// SMEM: E tile [128][68] f32 (34816 B), xib (256 B), part (2048 B).
// ---------------------------------------------------------------------------
#define XIB_OFF  34816
#define PART_OFF 35072
#define SMEM_MAIN_BYTES 37120

__global__ void __launch_bounds__(256, 3)
k_main(const float* __restrict__ E, const int* __restrict__ A,
       float* __restrict__ outE) {
    extern __shared__ __align__(16) char smem[];
    float* EsF  = (float*)smem;
    float* xib  = (float*)(smem + XIB_OFF);
    float* part = (float*)(smem + PART_OFF);
    const uint32_t sbase = smem_u32(smem);

    const int tid = threadIdx.x;
    const int lane = tid & 31, wid = tid >> 5;
    const int tile = blockIdx.x;
    const int i = tile >> 3, jt = tile & 7, j0 = jt << 7;

    // prefetch E tile [128 x 64] into padded smem (stride 68 floats)
    {
        const int row = tid >> 1, half = tid & 1;
        const float* src = E + ((size_t)i * NN + j0 + row) * FF + half * 32;
        const uint32_t dst = sbase + row * 272 + half * 128;
#pragma unroll
        for (int q = 0; q < 8; ++q)
            cp_async16(dst + q * 16, src + q * 4);
        CP_COMMIT();
    }
    if (tid < 16)
        ((float4*)xib)[tid] = *(const float4*)(g_XiB + i * FF + tid * 4);

    const int R0 = wid * 16 + (lane >> 2);   // rows R0 and R0+8
    const int acol = lane & 3;
    const int c2 = 2 * (lane & 3);

    const float amA = (float)__ldg(A + (size_t)i * NN + j0 + R0);
    const float amB = (float)__ldg(A + (size_t)i * NN + j0 + R0 + 8);

    CP_WAIT(0);
    __syncthreads();

    // ---- MMA: warp w -> rows [16w, 16w+16) x 64 cols ----
    float acc[8][4];
#pragma unroll
    for (int ni = 0; ni < 8; ++ni)
#pragma unroll
        for (int q = 0; q < 4; ++q) acc[ni][q] = 0.f;

#pragma unroll
    for (int k0 = 0; k0 < 8; ++k0) {
        uint32_t a[4];
        a[0] = f2tf32(EsF[R0 * 68 + k0 * 8 + acol]);
        a[1] = f2tf32(EsF[(R0 + 8) * 68 + k0 * 8 + acol]);
        a[2] = f2tf32(EsF[R0 * 68 + k0 * 8 + acol + 4]);
        a[3] = f2tf32(EsF[(R0 + 8) * 68 + k0 * 8 + acol + 4]);
#pragma unroll
        for (int ni = 0; ni < 8; ++ni) {
            const uint2 bb =
                __ldg((const uint2*)(g_Bfrag + (k0 * 8 + ni) * 64 + lane * 2));
            mma16n8k8(acc[ni], a, (const uint32_t*)&bb);
        }
    }

    // ---- register epilogue + column partial sums ----
    float cs0[8], cs1[8];
    const float* xjA = g_XjV + (size_t)(j0 + R0) * FF;
    const float* xjB = g_XjV + (size_t)(j0 + R0 + 8) * FF;
    float* obase = outE + ((size_t)i * NN + j0) * FF;
#pragma unroll
    for (int ni = 0; ni < 8; ++ni) {
        const int C = ni * 8 + c2;
        const float2 xb = *(const float2*)(xib + C);
        const float2 ja = __ldg((const float2*)(xjA + C));
        const float2 jb = __ldg((const float2*)(xjB + C));
        const float o0 = fmaxf(acc[ni][0] + ja.x + xb.x, 0.f) * amA;
        const float o1 = fmaxf(acc[ni][1] + ja.y + xb.y, 0.f) * amA;
        const float o2 = fmaxf(acc[ni][2] + jb.x + xb.x, 0.f) * amB;
        const float o3 = fmaxf(acc[ni][3] + jb.y + xb.y, 0.f) * amB;
        *(float2*)(obase + (size_t)R0 * FF + C) = make_float2(o0, o1);
        *(float2*)(obase + (size_t)(R0 + 8) * FF + C) = make_float2(o2, o3);
        cs0[ni] = o0 + o2;
        cs1[ni] = o1 + o3;
    }

    // shfl-reduce the warp's 16 rows (lanes differing in bits 2..4)
#pragma unroll
    for (int ni = 0; ni < 8; ++ni) {
#pragma unroll
        for (int ofs = 4; ofs < 32; ofs <<= 1) {
            cs0[ni] += __shfl_xor_sync(0xffffffffu, cs0[ni], ofs);
            cs1[ni] += __shfl_xor_sync(0xffffffffu, cs1[ni], ofs);
        }
    }
    if (lane < 4) {
#pragma unroll
        for (int ni = 0; ni < 8; ++ni)
            *(float2*)&part[wid * 64 + ni * 8 + lane * 2] =
                make_float2(cs0[ni], cs1[ni]);
    }
    __syncthreads();
    if (tid < 64) {
        float s = part[tid];
#pragma unroll
        for (int w = 1; w < 8; ++w) s += part[w * 64 + tid];
        g_part[((size_t)i * 8 + jt) * 64 + tid] = s;
    }
}

// ---------------------------------------------------------------------------
// Kernel 3: E_agg + node GEMM. grid = 256 x 256, 4 rows per CTA.
// ---------------------------------------------------------------------------
__global__ void __launch_bounds__(256)
k_final(const float* __restrict__ X, const float* __restrict__ Wn,
        const float* __restrict__ bn, float* __restrict__ outX) {
    __shared__ float Wns[8192];
    __shared__ float Xs[256];
    __shared__ float Es[256];
    __shared__ float bns[64];
    const int b = blockIdx.x, t = threadIdx.x;
    const int r0 = b * 4;

    {
        const float4* src = (const float4*)Wn;
        float4* dst = (float4*)Wns;
#pragma unroll
        for (int it = 0; it < 8; ++it) dst[it * 256 + t] = src[it * 256 + t];
    }
    if (t < 64) ((float4*)Xs)[t] = *(const float4*)(X + r0 * 64 + t * 4);
    {
        const int r = t >> 6, c = t & 63;
        float s = 0.f;
#pragma unroll
        for (int j = 0; j < 8; ++j)
            s += g_part[((size_t)(r0 + r) * 8 + j) * 64 + c];
        Es[t] = s;
        if (t < 64) bns[t] = bn[t];
    }
    __syncthreads();

    const int r = t >> 6, col = t & 63;
    float acc = bns[col];
#pragma unroll 16
    for (int k = 0; k < 64; ++k)
        acc += Xs[r * 64 + k] * Wns[k * 64 + col];
#pragma unroll 16
    for (int k = 0; k < 64; ++k)
        acc += Es[r * 64 + k] * Wns[(64 + k) * 64 + col];
    outX[(r0 + r) * 64 + col] = fmaxf(acc, 0.f);
}

// ---------------------------------------------------------------------------
extern "C" void kernel_launch(void* const* d_in, const int* in_sizes, int n_in,
                              void* d_out, int out_size) {
    const float* X  = (const float*)d_in[0];
    const float* E  = (const float*)d_in[1];
    const int*   A  = (const int*)d_in[2];
    const float* We = (const float*)d_in[3];
    const float* be = (const float*)d_in[4];
    const float* Wn = (const float*)d_in[5];
    const float* bn = (const float*)d_in[6];
    float* out = (float*)d_out;

    (void)in_sizes; (void)n_in; (void)out_size;

    cudaFuncSetAttribute(k_main, cudaFuncAttributeMaxDynamicSharedMemorySize,
                         SMEM_MAIN_BYTES);

    k_prep<<<257, 256>>>(X, We, be);
    k_main<<<8192, 256, SMEM_MAIN_BYTES>>>(E, A, out + NN * FF);
    k_final<<<256, 256>>>(X, Wn, bn, out);
}

// round 11
// speedup vs baseline: 1.2829x; 1.2829x over previous
#include <cuda_runtime.h>
#include <cstdint>
#include <cstddef>

// ============================================================================
// WeaveLayer on sm_100 (no 'a' features): mma.sync m16n8k8 tf32 engine.
//   h = E@We_E + (X@We_Xi)[i] + (X@We_Xj)[j] + be
//   E_new = relu(h)*A ; E_agg[i] = sum_j E_new[i,j]
//   X_new = relu(X@Wn_X + E_agg@Wn_E + bn)
// Output: X_new (65536 f32) then E_new (67108864 f32).
// R9: R4-layout k_main (best measured) + wide prep/final (measured good).
// k_nop dropped — restores the R6-proven 3-launch structure.
// ============================================================================

#define NN 1024
#define FF 64

__device__ float g_XiB[NN * FF];       // X@We_Xi + be
__device__ float g_XjV[NN * FF];       // X@We_Xj
__device__ float g_Bfrag[64 * 64];     // mma-fragment-ordered tf32 We_E
__device__ float g_part[NN * 8 * FF];  // per (i, j-tile) partial E_agg

// ---------------------------------------------------------------------------
static __device__ __forceinline__ uint32_t smem_u32(const void* p) {
    uint32_t a;
    asm("{ .reg .u64 t; cvta.to.shared.u64 t, %1; cvt.u32.u64 %0, t; }"
        : "=r"(a) : "l"(p));
    return a;
}
static __device__ __forceinline__ uint32_t f2tf32(float x) {
    uint32_t r;
    asm("cvt.rna.tf32.f32 %0, %1;" : "=r"(r) : "f"(x));
    return r;
}
static __device__ __forceinline__ void mma16n8k8(float* c, const uint32_t* a,
                                                 const uint32_t* b) {
    asm volatile(
        "mma.sync.aligned.m16n8k8.row.col.f32.tf32.tf32.f32 "
        "{%0,%1,%2,%3}, {%4,%5,%6,%7}, {%8,%9}, {%0,%1,%2,%3};"
        : "+f"(c[0]), "+f"(c[1]), "+f"(c[2]), "+f"(c[3])
        : "r"(a[0]), "r"(a[1]), "r"(a[2]), "r"(a[3]), "r"(b[0]), "r"(b[1]));
}
static __device__ __forceinline__ void cp_async16(uint32_t dst, const void* src) {
    asm volatile("cp.async.cg.shared.global [%0], [%1], 16;"
                 :: "r"(dst), "l"(src) : "memory");
}
#define CP_COMMIT() asm volatile("cp.async.commit_group;" ::: "memory")
#define CP_WAIT(n)  asm volatile("cp.async.wait_group %0;" :: "n"(n) : "memory")

// ---------------------------------------------------------------------------
// Kernel 1: XiB/XjV + B fragment image. grid = 257 x 256.
// CTA b<256: rows [4b, 4b+4). CTA 256: B fragment image.
// ---------------------------------------------------------------------------
__global__ void __launch_bounds__(256)
k_prep(const float* __restrict__ X, const float* __restrict__ We,
       const float* __restrict__ be) {
    const int b = blockIdx.x, t = threadIdx.x;

    if (b == 256) {
        // g_Bfrag[(k0*8+ni)*64 + lane*2 + h] = tf32(We_E[k0*8+bk+4h][ni*8+bn])
        const int lane = t & 31, grp = t >> 5;
        const int bk = lane & 3, bn = lane >> 2;
        for (int f = grp; f < 64; f += 8) {
            const int k0 = f >> 3, ni = f & 7;
            g_Bfrag[f * 64 + lane * 2 + 0] =
                __uint_as_float(f2tf32(We[(k0 * 8 + bk) * 64 + ni * 8 + bn]));
            g_Bfrag[f * 64 + lane * 2 + 1] =
                __uint_as_float(f2tf32(We[(k0 * 8 + bk + 4) * 64 + ni * 8 + bn]));
        }
        return;
    }

    __shared__ float Ws[8192];   // We_Xi (0..4095), We_Xj (4096..8191)
    __shared__ float Xs[256];
    __shared__ float bes[64];
    const int r0 = b * 4;

    {
        const float4* src = (const float4*)(We + 4096);
        float4* dst = (float4*)Ws;
#pragma unroll
        for (int it = 0; it < 8; ++it) dst[it * 256 + t] = src[it * 256 + t];
    }
    if (t < 64) {
        ((float4*)Xs)[t] = *(const float4*)(X + r0 * 64 + t * 4);
        bes[t] = be[t];
    }
    __syncthreads();

    const int r = t >> 6, col = t & 63;
    float ai = bes[col], aj = 0.f;
#pragma unroll 16
    for (int k = 0; k < 64; ++k) {
        const float v = Xs[r * 64 + k];
        ai += v * Ws[k * 64 + col];
        aj += v * Ws[4096 + k * 64 + col];
    }
    g_XiB[(r0 + r) * 64 + col] = ai;
    g_XjV[(r0 + r) * 64 + col] = aj;
}

// ---------------------------------------------------------------------------
// Kernel 2: edge kernel (R4 layout). One CTA per (i, 128-wide j-tile) =
// 8192 CTAs, 128 threads (4 warps, warp w owns rows [32w, 32w+32)).
// SMEM: E tile [128][68] f32 at 0..34816, part 1KB at 34816.
// ---------------------------------------------------------------------------
#define PART_OFF 34816
#define SMEM_MAIN_BYTES 35840

__global__ void __launch_bounds__(128, 4)
k_main(const float* __restrict__ E, const int* __restrict__ A,
       float* __restrict__ outE) {
    extern __shared__ __align__(16) char smem[];
    float* EsF  = (float*)smem;
    float* part = (float*)(smem + PART_OFF);
    const uint32_t sbase = smem_u32(smem);

    const int tid = threadIdx.x;
    const int lane = tid & 31, wid = tid >> 5;
    const int tile = blockIdx.x;
    const int i = tile >> 3, jt = tile & 7, j0 = jt << 7;

    // prefetch E tile [128 x 64] into padded smem (stride 68 floats)
    {
        const int ldrow = tid >> 4, ldq = tid & 15;
        const float* src = E + ((size_t)i * NN + j0 + ldrow) * FF + ldq * 4;
        const uint32_t dst = sbase + ldrow * 272 + ldq * 16;
#pragma unroll
        for (int it = 0; it < 16; ++it)
            cp_async16(dst + it * 8 * 272, src + (size_t)it * 8 * FF);
        CP_COMMIT();
    }

    // per-thread constants while the tile is in flight
    const int R0 = wid * 32 + (lane >> 2);   // first of this thread's 4 rows
    const int acol = lane & 3;
    const int c2 = 2 * (lane & 3);

    float xib0[8], xib1[8];
    {
        const float* xb = g_XiB + i * FF;
#pragma unroll
        for (int ni = 0; ni < 8; ++ni) {
            const float2 v = __ldg((const float2*)(xb + ni * 8 + c2));
            xib0[ni] = v.x; xib1[ni] = v.y;
        }
    }
    float am[4];
#pragma unroll
    for (int mi = 0; mi < 2; ++mi) {
        am[mi * 2 + 0] = (float)__ldg(A + (size_t)i * NN + j0 + R0 + mi * 16);
        am[mi * 2 + 1] = (float)__ldg(A + (size_t)i * NN + j0 + R0 + mi * 16 + 8);
    }

    CP_WAIT(0);
    __syncthreads();

    // ---- MMA: warp w -> rows [32w, 32w+32) x 64 cols ----
    float acc[2][8][4];
#pragma unroll
    for (int mi = 0; mi < 2; ++mi)
#pragma unroll
        for (int ni = 0; ni < 8; ++ni)
#pragma unroll
            for (int q = 0; q < 4; ++q) acc[mi][ni][q] = 0.f;

#pragma unroll
    for (int k0 = 0; k0 < 8; ++k0) {
        uint2 bb[8];
#pragma unroll
        for (int ni = 0; ni < 8; ++ni)
            bb[ni] = __ldg((const uint2*)(g_Bfrag + (k0 * 8 + ni) * 64 + lane * 2));
#pragma unroll
        for (int mi = 0; mi < 2; ++mi) {
            const int r = R0 + mi * 16;
            uint32_t a[4];
            a[0] = f2tf32(EsF[r * 68 + k0 * 8 + acol]);
            a[1] = f2tf32(EsF[(r + 8) * 68 + k0 * 8 + acol]);
            a[2] = f2tf32(EsF[r * 68 + k0 * 8 + acol + 4]);
            a[3] = f2tf32(EsF[(r + 8) * 68 + k0 * 8 + acol + 4]);
#pragma unroll
            for (int ni = 0; ni < 8; ++ni)
                mma16n8k8(acc[mi][ni], a, (const uint32_t*)&bb[ni]);
        }
    }

    // ---- register epilogue + column partial sums ----
    float cs0[8], cs1[8];
#pragma unroll
    for (int ni = 0; ni < 8; ++ni) { cs0[ni] = 0.f; cs1[ni] = 0.f; }

    float* obase = outE + ((size_t)i * NN + j0) * FF;
#pragma unroll
    for (int mi = 0; mi < 2; ++mi) {
        const int rA = R0 + mi * 16, rB = rA + 8;
        const float* xjA = g_XjV + (size_t)(j0 + rA) * FF;
        const float* xjB = g_XjV + (size_t)(j0 + rB) * FF;
        const float aA = am[mi * 2 + 0], aB = am[mi * 2 + 1];
#pragma unroll
        for (int ni = 0; ni < 8; ++ni) {
            const int C = ni * 8 + c2;
            const float2 ja = __ldg((const float2*)(xjA + C));
            const float2 jb = __ldg((const float2*)(xjB + C));
            const float o0 = fmaxf(acc[mi][ni][0] + ja.x + xib0[ni], 0.f) * aA;
            const float o1 = fmaxf(acc[mi][ni][1] + ja.y + xib1[ni], 0.f) * aA;
            const float o2 = fmaxf(acc[mi][ni][2] + jb.x + xib0[ni], 0.f) * aB;
            const float o3 = fmaxf(acc[mi][ni][3] + jb.y + xib1[ni], 0.f) * aB;
            *(float2*)(obase + (size_t)rA * FF + C) = make_float2(o0, o1);
            *(float2*)(obase + (size_t)rB * FF + C) = make_float2(o2, o3);
            cs0[ni] += o0 + o2;
            cs1[ni] += o1 + o3;
        }
    }

    // shfl-reduce over the 8 row-groups (lanes differing in bits 2..4)
#pragma unroll
    for (int ni = 0; ni < 8; ++ni) {
#pragma unroll
        for (int ofs = 4; ofs < 32; ofs <<= 1) {
            cs0[ni] += __shfl_xor_sync(0xffffffffu, cs0[ni], ofs);
            cs1[ni] += __shfl_xor_sync(0xffffffffu, cs1[ni], ofs);
        }
    }
    if (lane < 4) {
#pragma unroll
        for (int ni = 0; ni < 8; ++ni)
            *(float2*)&part[wid * 64 + ni * 8 + lane * 2] =
                make_float2(cs0[ni], cs1[ni]);
    }
    __syncthreads();
    if (tid < 64)
        g_part[((size_t)i * 8 + jt) * 64 + tid] =
            (part[tid] + part[64 + tid]) + (part[128 + tid] + part[192 + tid]);
}

// ---------------------------------------------------------------------------
// Kernel 3: E_agg + node GEMM. grid = 256 x 256, 4 rows per CTA.
// ---------------------------------------------------------------------------
__global__ void __launch_bounds__(256)
k_final(const float* __restrict__ X, const float* __restrict__ Wn,
        const float* __restrict__ bn, float* __restrict__ outX) {
    __shared__ float Wns[8192];
    __shared__ float Xs[256];
    __shared__ float Es[256];
    __shared__ float bns[64];
    const int b = blockIdx.x, t = threadIdx.x;
    const int r0 = b * 4;

    {
        const float4* src = (const float4*)Wn;
        float4* dst = (float4*)Wns;
#pragma unroll
        for (int it = 0; it < 8; ++it) dst[it * 256 + t] = src[it * 256 + t];
    }
    if (t < 64) ((float4*)Xs)[t] = *(const float4*)(X + r0 * 64 + t * 4);
    {
        const int r = t >> 6, c = t & 63;
        float s = 0.f;
#pragma unroll
        for (int j = 0; j < 8; ++j)
            s += g_part[((size_t)(r0 + r) * 8 + j) * 64 + c];
        Es[t] = s;
        if (t < 64) bns[t] = bn[t];
    }
    __syncthreads();

    const int r = t >> 6, col = t & 63;
    float acc = bns[col];
#pragma unroll 16
    for (int k = 0; k < 64; ++k)
        acc += Xs[r * 64 + k] * Wns[k * 64 + col];
#pragma unroll 16
    for (int k = 0; k < 64; ++k)
        acc += Es[r * 64 + k] * Wns[(64 + k) * 64 + col];
    outX[(r0 + r) * 64 + col] = fmaxf(acc, 0.f);
}

// ---------------------------------------------------------------------------
extern "C" void kernel_launch(void* const* d_in, const int* in_sizes, int n_in,
                              void* d_out, int out_size) {
    const float* X  = (const float*)d_in[0];
    const float* E  = (const float*)d_in[1];
    const int*   A  = (const int*)d_in[2];
    const float* We = (const float*)d_in[3];
    const float* be = (const float*)d_in[4];
    const float* Wn = (const float*)d_in[5];
    const float* bn = (const float*)d_in[6];
    float* out = (float*)d_out;

    (void)in_sizes; (void)n_in; (void)out_size;

    cudaFuncSetAttribute(k_main, cudaFuncAttributeMaxDynamicSharedMemorySize,
                         SMEM_MAIN_BYTES);

    k_prep<<<257, 256>>>(X, We, be);
    k_main<<<8192, 128, SMEM_MAIN_BYTES>>>(E, A, out + NN * FF);
    k_final<<<256, 256>>>(X, Wn, bn, out);
}